// round 7
// baseline (speedup 1.0000x reference)
#include <cuda_runtime.h>
#include <cuda_fp16.h>
#include <cstdint>

#define NB 64
#define CCH 128
#define HW 1024
#define PER_N (CCH*HW)          // 131072
#define PER_T (NB*PER_N)        // 8388608
#define S_SCALE 0.08838834764831845f   // 1/sqrt(128)

// Scratch (device globals: allocation-free per harness rules)
__device__ __half g_projh[3u*PER_T];   // Q_T [n][j][c], K_T(scaled) [n][i][c], V [n][c][i]
__device__ float2 g_stats[3*NB];       // (mu, rstd) per (t, n)
__device__ float2 g_part[3*NB*4];      // partial (sum, sumsq)

// ---------------------------------------------------------------------------
// helpers
// ---------------------------------------------------------------------------
__device__ __forceinline__ uint32_t f2tf32(float x) {
    uint32_t u; asm("cvt.rna.tf32.f32 %0, %1;" : "=r"(u) : "f"(x)); return u;
}
__device__ __forceinline__ void mma_tf32(float c[4],
    uint32_t a0, uint32_t a1, uint32_t a2, uint32_t a3, uint32_t b0, uint32_t b1)
{
    asm volatile(
        "mma.sync.aligned.m16n8k8.row.col.f32.tf32.tf32.f32 "
        "{%0,%1,%2,%3},{%4,%5,%6,%7},{%8,%9},{%0,%1,%2,%3};"
        : "+f"(c[0]), "+f"(c[1]), "+f"(c[2]), "+f"(c[3])
        : "r"(a0), "r"(a1), "r"(a2), "r"(a3), "r"(b0), "r"(b1));
}
__device__ __forceinline__ void mma_f16(float c[4],
    uint32_t a0, uint32_t a1, uint32_t a2, uint32_t a3, uint32_t b0, uint32_t b1)
{
    asm volatile(
        "mma.sync.aligned.m16n8k16.row.col.f32.f16.f16.f32 "
        "{%0,%1,%2,%3},{%4,%5,%6,%7},{%8,%9},{%0,%1,%2,%3};"
        : "+f"(c[0]), "+f"(c[1]), "+f"(c[2]), "+f"(c[3])
        : "r"(a0), "r"(a1), "r"(a2), "r"(a3), "r"(b0), "r"(b1));
}
__device__ __forceinline__ void ldsm_x4(uint32_t r[4], uint32_t addr) {
    asm volatile("ldmatrix.sync.aligned.m8n8.x4.shared.b16 {%0,%1,%2,%3}, [%4];"
        : "=r"(r[0]), "=r"(r[1]), "=r"(r[2]), "=r"(r[3]) : "r"(addr));
}
__device__ __forceinline__ void cp16(uint32_t dst_smem, const void* src) {
    asm volatile("cp.async.ca.shared.global [%0], [%1], 16;"
                 :: "r"(dst_smem), "l"(src) : "memory");
}
__device__ __forceinline__ void cp_commit() {
    asm volatile("cp.async.commit_group;" ::: "memory");
}
__device__ __forceinline__ void cp_wait0() {
    asm volatile("cp.async.wait_group 0;" ::: "memory");
}

// ---------------------------------------------------------------------------
// LN partial sums: grid (64, 3, 4), 256 threads; each covers PER_N/4 elems
// ---------------------------------------------------------------------------
__global__ __launch_bounds__(256) void ln_part_kernel(
    const float* __restrict__ q, const float* __restrict__ k, const float* __restrict__ v)
{
    int n = blockIdx.x, t = blockIdx.y, p = blockIdx.z;
    const float* x = (t == 0) ? q : (t == 1) ? k : v;
    const float4* x4 = reinterpret_cast<const float4*>(x + (size_t)n * PER_N) + p * (PER_N / 16);

    float s = 0.f, ss = 0.f;
    for (int i = threadIdx.x; i < PER_N / 16; i += 256) {
        float4 u = x4[i];
        s  += u.x + u.y + u.z + u.w;
        ss += u.x * u.x + u.y * u.y + u.z * u.z + u.w * u.w;
    }
    __shared__ float sh_s[8], sh_ss[8];
    for (int off = 16; off > 0; off >>= 1) {
        s  += __shfl_down_sync(0xffffffffu, s, off);
        ss += __shfl_down_sync(0xffffffffu, ss, off);
    }
    int warp = threadIdx.x >> 5, lane = threadIdx.x & 31;
    if (lane == 0) { sh_s[warp] = s; sh_ss[warp] = ss; }
    __syncthreads();
    if (warp == 0) {
        s  = (lane < 8) ? sh_s[lane]  : 0.f;
        ss = (lane < 8) ? sh_ss[lane] : 0.f;
        for (int off = 4; off > 0; off >>= 1) {
            s  += __shfl_down_sync(0xffffffffu, s, off);
            ss += __shfl_down_sync(0xffffffffu, ss, off);
        }
        if (lane == 0) g_part[(t * NB + n) * 4 + p] = make_float2(s, ss);
    }
}

// finalize: 1 block, 192 threads
__global__ void ln_finalize_kernel()
{
    int i = threadIdx.x;   // t*64+n
    if (i < 3 * NB) {
        float s = 0.f, ss = 0.f;
#pragma unroll
        for (int p = 0; p < 4; p++) {
            float2 u = g_part[i * 4 + p];
            s += u.x; ss += u.y;
        }
        float mu  = s * (1.f / (float)PER_N);
        float var = ss * (1.f / (float)PER_N) - mu * mu;
        g_stats[i] = make_float2(mu, rsqrtf(var + 1e-5f));
    }
}

// ---------------------------------------------------------------------------
// conv 1x1 via tf32 mma with LN fused into B staging:
//   Xn[c,j] = (X[c,j]-mu)*rstd*lw[c,j]+lb[c,j];  Y[o,j] = W[o,c] Xn[c,j] + bias[o]
// Outputs half, t=0: Q_T[j][o], t=1: K_T[i][o] * S_SCALE, t=2: V[o][i]
// grid (8, 1, 192) z=t*64+n, 256 threads, tile 128x128, BK=32
// ---------------------------------------------------------------------------
__global__ __launch_bounds__(256) void conv_mma_kernel(
    const float* __restrict__ q, const float* __restrict__ k, const float* __restrict__ v,
    const float* __restrict__ ln1w, const float* __restrict__ ln1b,
    const float* __restrict__ ln2w, const float* __restrict__ ln2b,
    const float* __restrict__ ln3w, const float* __restrict__ ln3b,
    const float* __restrict__ wq, const float* __restrict__ bq,
    const float* __restrict__ wk, const float* __restrict__ bk,
    const float* __restrict__ wv, const float* __restrict__ bv)
{
    int t = blockIdx.z >> 6, n = blockIdx.z & 63;
    const float* W  = (t == 0) ? wq : (t == 1) ? wk : wv;
    const float* Bi = (t == 0) ? bq : (t == 1) ? bk : bv;
    const float* Xr = ((t == 0) ? q : (t == 1) ? k : v) + (size_t)n * PER_N;
    const float* LW = (t == 0) ? ln1w : (t == 1) ? ln2w : ln3w;
    const float* LB = (t == 0) ? ln1b : (t == 1) ? ln2b : ln3b;
    float2 st = g_stats[t * NB + n];
    float mu = st.x, rstd = st.y;
    int j0 = blockIdx.x * 128;

    __shared__ union {
        struct { uint32_t As[128][36]; uint32_t Bs[32][136]; } s;
        __half ep[128][136];
    } u;

    int tid = threadIdx.x, lane = tid & 31, warp = tid >> 5;
    int g = lane >> 2, t4 = lane & 3;
    int wm = (warp >> 2) * 64, wn = (warp & 3) * 32;

    float acc[4][4][4];
#pragma unroll
    for (int a = 0; a < 4; a++)
#pragma unroll
        for (int b2 = 0; b2 < 4; b2++)
#pragma unroll
            for (int e = 0; e < 4; e++) acc[a][b2][e] = 0.f;

    for (int k0 = 0; k0 < 128; k0 += 32) {
#pragma unroll
        for (int r = 0; r < 4; r++) {
            int lin = tid + r * 256;
            int m = lin >> 3, k4 = lin & 7;
            float4 vv = *(const float4*)&W[m * 128 + k0 + k4 * 4];
            uint4 uu = make_uint4(f2tf32(vv.x), f2tf32(vv.y), f2tf32(vv.z), f2tf32(vv.w));
            *(uint4*)&u.s.As[m][k4 * 4] = uu;
        }
#pragma unroll
        for (int r = 0; r < 4; r++) {
            int lin = tid + r * 256;
            int row = lin >> 5, c4 = lin & 31;
            int idx = (k0 + row) * 1024 + j0 + c4 * 4;
            float4 xv = *(const float4*)&Xr[idx];
            float4 lw = *(const float4*)&LW[idx];
            float4 lb = *(const float4*)&LB[idx];
            float n0 = (xv.x - mu) * rstd * lw.x + lb.x;
            float n1 = (xv.y - mu) * rstd * lw.y + lb.y;
            float n2 = (xv.z - mu) * rstd * lw.z + lb.z;
            float n3 = (xv.w - mu) * rstd * lw.w + lb.w;
            uint4 uu = make_uint4(f2tf32(n0), f2tf32(n1), f2tf32(n2), f2tf32(n3));
            *(uint4*)&u.s.Bs[row][c4 * 4] = uu;
        }
        __syncthreads();
#pragma unroll
        for (int ks = 0; ks < 4; ks++) {
            int kl = ks * 8 + t4, kh = kl + 4;
            uint32_t af[4][4], bf[4][2];
#pragma unroll
            for (int mt = 0; mt < 4; mt++) {
                int mb = wm + mt * 16 + g;
                af[mt][0] = u.s.As[mb][kl];     af[mt][1] = u.s.As[mb + 8][kl];
                af[mt][2] = u.s.As[mb][kh];     af[mt][3] = u.s.As[mb + 8][kh];
            }
#pragma unroll
            for (int nt = 0; nt < 4; nt++) {
                int nb = wn + nt * 8 + g;
                bf[nt][0] = u.s.Bs[kl][nb];     bf[nt][1] = u.s.Bs[kh][nb];
            }
#pragma unroll
            for (int mt = 0; mt < 4; mt++)
#pragma unroll
                for (int nt = 0; nt < 4; nt++)
                    mma_tf32(acc[mt][nt], af[mt][0], af[mt][1], af[mt][2], af[mt][3],
                             bf[nt][0], bf[nt][1]);
        }
        __syncthreads();
    }

    // Stage epilogue tile into smem (half) in the target layout
    float sc = (t == 1) ? S_SCALE : 1.f;
#pragma unroll
    for (int mt = 0; mt < 4; mt++) {
        int m0 = wm + mt * 16 + g;
        float bias0 = Bi[m0], bias1 = Bi[m0 + 8];
#pragma unroll
        for (int nt = 0; nt < 4; nt++) {
            int jl = wn + nt * 8 + t4 * 2;
            float v0 = (acc[mt][nt][0] + bias0) * sc;
            float v1 = (acc[mt][nt][1] + bias0) * sc;
            float v2 = (acc[mt][nt][2] + bias1) * sc;
            float v3 = (acc[mt][nt][3] + bias1) * sc;
            if (t < 2) {   // transposed: ep[j][o]
                u.ep[jl][m0]         = __float2half(v0);
                u.ep[jl + 1][m0]     = __float2half(v1);
                u.ep[jl][m0 + 8]     = __float2half(v2);
                u.ep[jl + 1][m0 + 8] = __float2half(v3);
            } else {       // natural: ep[o][j]
                u.ep[m0][jl]         = __float2half(v0);
                u.ep[m0][jl + 1]     = __float2half(v1);
                u.ep[m0 + 8][jl]     = __float2half(v2);
                u.ep[m0 + 8][jl + 1] = __float2half(v3);
            }
        }
    }
    __syncthreads();

    __half* dst = g_projh + (size_t)t * PER_T + (size_t)n * PER_N;
    if (t < 2) {
#pragma unroll
        for (int r = 0; r < 8; r++) {
            int lin = tid + r * 256;
            int row = lin >> 4, off = lin & 15;
            *(uint4*)&dst[(size_t)(j0 + row) * 128 + off * 8] = *(uint4*)&u.ep[row][off * 8];
        }
    } else {
#pragma unroll
        for (int r = 0; r < 8; r++) {
            int lin = tid + r * 256;
            int row = lin >> 4, off = lin & 15;
            *(uint4*)&dst[(size_t)row * 1024 + j0 + off * 8] = *(uint4*)&u.ep[row][off * 8];
        }
    }
}

// ---------------------------------------------------------------------------
// Fused attention, ldmatrix operand path.
// grid (8, 64), 256 threads
// ---------------------------------------------------------------------------
#define TS 136                      // smem row stride (halfs)
#define TILE_H (128 * TS)           // halfs per 128-row tile
#define FUSED_SMEM (( (size_t)6 * TILE_H ) * 2 + 4*128*4 + 128*4)

__global__ __launch_bounds__(256, 1) void fused_attn_kernel(
    float* __restrict__ out,
    const float* __restrict__ qraw,
    const float* __restrict__ ln1w, const float* __restrict__ ln1b)
{
    extern __shared__ __align__(16) char smem_raw[];
    __half* Qs = (__half*)smem_raw;        // [128][TS]
    __half* Ks = Qs + TILE_H;              // [2][128][TS]
    __half* Vs = Ks + 2 * TILE_H;          // [2][128][TS]
    __half* Et = Vs + 2 * TILE_H;          // [128][TS]  (E transposed: [j][i])
    float*  red = (float*)(Et + TILE_H);   // [4][128]
    float*  inv = red + 4 * 128;           // [128]

    int n = blockIdx.y, j0 = blockIdx.x * 128;
    const __half* Qh = g_projh + (size_t)n * PER_N;                // [j][c]
    const __half* Kh = g_projh + PER_T + (size_t)n * PER_N;        // [i][c] (scaled)
    const __half* Vh = g_projh + 2u * PER_T + (size_t)n * PER_N;   // [c][i]
    const float*  Qr = qraw + (size_t)n * PER_N;
    float2 st = g_stats[n];                                        // t = 0
    float mu = st.x, rstd = st.y;

    int tid = threadIdx.x, lane = tid & 31, warp = tid >> 5;
    int g = lane >> 2, t4 = lane & 3;
    int wi = warp >> 1, wj = warp & 1;

    // ldmatrix per-lane addressing: row = base + (lane&15), col += (lane>>4)*8
    int rL = lane & 15, cL = (lane >> 4) * 8;

    uint32_t qs_b = (uint32_t)__cvta_generic_to_shared(Qs);
    uint32_t ks_b = (uint32_t)__cvta_generic_to_shared(Ks);
    uint32_t vs_b = (uint32_t)__cvta_generic_to_shared(Vs);
    uint32_t et_b = (uint32_t)__cvta_generic_to_shared(Et);

    // prefetch Q + K0 + V0
#pragma unroll
    for (int r = 0; r < 8; r++) {
        int lin = tid + r * 256;
        int row = lin >> 4, off = lin & 15;
        uint32_t so = (uint32_t)(row * TS + off * 8) * 2u;
        cp16(qs_b + so, Qh + (size_t)(j0 + row) * 128 + off * 8);
        cp16(ks_b + so, Kh + (size_t)row * 128 + off * 8);
        cp16(vs_b + so, Vh + (size_t)row * 1024 + off * 8);
    }
    cp_commit();

    float oacc[2][8][4];
#pragma unroll
    for (int a = 0; a < 2; a++)
#pragma unroll
        for (int b2 = 0; b2 < 8; b2++)
#pragma unroll
            for (int e = 0; e < 4; e++) oacc[a][b2][e] = 0.f;
    float psum[8][2];
#pragma unroll
    for (int a = 0; a < 8; a++) { psum[a][0] = 0.f; psum[a][1] = 0.f; }

    cp_wait0();
    __syncthreads();

    for (int it = 0; it < 8; it++) {
        int buf = it & 1, nbuf = buf ^ 1;
        if (it < 7) {  // prefetch next K/V tile
#pragma unroll
            for (int r = 0; r < 8; r++) {
                int lin = tid + r * 256;
                int row = lin >> 4, off = lin & 15;
                uint32_t so = (uint32_t)(nbuf * TILE_H + row * TS + off * 8) * 2u;
                cp16(ks_b + so, Kh + (size_t)((it + 1) * 128 + row) * 128 + off * 8);
                cp16(vs_b + so, Vh + (size_t)row * 1024 + (it + 1) * 128 + off * 8);
            }
            cp_commit();
        }

        // ---- MMA1: S[i_local, j_local] over k=c=128 (ldmatrix operands) ----
        uint32_t kbuf = ks_b + (uint32_t)(buf * TILE_H) * 2u;
        float sacc[2][8][4];
#pragma unroll
        for (int a = 0; a < 2; a++)
#pragma unroll
            for (int b2 = 0; b2 < 8; b2++)
#pragma unroll
                for (int e = 0; e < 4; e++) sacc[a][b2][e] = 0.f;

#pragma unroll
        for (int kk = 0; kk < 8; kk++) {
            int kb0 = kk * 16 + cL;
            uint32_t a[2][4], b[4][4];
#pragma unroll
            for (int mt = 0; mt < 2; mt++)
                ldsm_x4(a[mt], kbuf + (uint32_t)((wi * 32 + mt * 16 + rL) * TS + kb0) * 2u);
#pragma unroll
            for (int np = 0; np < 4; np++)
                ldsm_x4(b[np], qs_b + (uint32_t)((wj * 64 + np * 16 + rL) * TS + kb0) * 2u);
#pragma unroll
            for (int mt = 0; mt < 2; mt++)
#pragma unroll
                for (int np = 0; np < 4; np++) {
                    mma_f16(sacc[mt][np * 2],     a[mt][0], a[mt][1], a[mt][2], a[mt][3],
                            b[np][0], b[np][2]);
                    mma_f16(sacc[mt][np * 2 + 1], a[mt][0], a[mt][1], a[mt][2], a[mt][3],
                            b[np][1], b[np][3]);
                }
        }

        // ---- exp + write E^T + column partial sums ----
#pragma unroll
        for (int mt = 0; mt < 2; mt++) {
            int ib = wi * 32 + mt * 16 + g;
#pragma unroll
            for (int nt = 0; nt < 8; nt++) {
                int jr = wj * 64 + nt * 8 + t4 * 2;
                float e0 = __expf(fminf(sacc[mt][nt][0], 11.f));
                float e1 = __expf(fminf(sacc[mt][nt][1], 11.f));
                float e2 = __expf(fminf(sacc[mt][nt][2], 11.f));
                float e3 = __expf(fminf(sacc[mt][nt][3], 11.f));
                psum[nt][0] += e0 + e2;
                psum[nt][1] += e1 + e3;
                Et[jr * TS + ib]           = __float2half(e0);
                Et[(jr + 1) * TS + ib]     = __float2half(e1);
                Et[jr * TS + ib + 8]       = __float2half(e2);
                Et[(jr + 1) * TS + ib + 8] = __float2half(e3);
            }
        }
        __syncthreads();

        // ---- MMA2: oacc[c, j] += V[c, i] * E[i, j]  (ldmatrix operands) ----
        uint32_t vbuf = vs_b + (uint32_t)(buf * TILE_H) * 2u;
#pragma unroll
        for (int kk = 0; kk < 8; kk++) {
            int kb0 = kk * 16 + cL;
            uint32_t a[2][4], b[4][4];
#pragma unroll
            for (int mt = 0; mt < 2; mt++)
                ldsm_x4(a[mt], vbuf + (uint32_t)((wi * 32 + mt * 16 + rL) * TS + kb0) * 2u);
#pragma unroll
            for (int np = 0; np < 4; np++)
                ldsm_x4(b[np], et_b + (uint32_t)((wj * 64 + np * 16 + rL) * TS + kb0) * 2u);
#pragma unroll
            for (int mt = 0; mt < 2; mt++)
#pragma unroll
                for (int np = 0; np < 4; np++) {
                    mma_f16(oacc[mt][np * 2],     a[mt][0], a[mt][1], a[mt][2], a[mt][3],
                            b[np][0], b[np][2]);
                    mma_f16(oacc[mt][np * 2 + 1], a[mt][0], a[mt][1], a[mt][2], a[mt][3],
                            b[np][1], b[np][3]);
                }
        }

        if (it < 7) cp_wait0();
        __syncthreads();
    }

    // ---- column-sum reduce: over g within warp, over wi via smem ----
#pragma unroll
    for (int nt = 0; nt < 8; nt++) {
#pragma unroll
        for (int e = 0; e < 2; e++) {
            float v = psum[nt][e];
            v += __shfl_down_sync(0xffffffffu, v, 16);
            v += __shfl_down_sync(0xffffffffu, v, 8);
            v += __shfl_down_sync(0xffffffffu, v, 4);
            if (lane < 4)
                red[wi * 128 + wj * 64 + nt * 8 + lane * 2 + e] = v;
        }
    }
    __syncthreads();
    if (tid < 128)
        inv[tid] = 1.f / (red[tid] + red[128 + tid] + red[256 + tid] + red[384 + tid]);
    __syncthreads();

    // ---- epilogue: normalize + residual (qn recomputed from raw q) ----
    float* outp = out + (size_t)n * PER_N;
#pragma unroll
    for (int mt = 0; mt < 2; mt++) {
        int c0r = wi * 32 + mt * 16 + g;
#pragma unroll
        for (int nt = 0; nt < 8; nt++) {
            int jl = wj * 64 + nt * 8 + t4 * 2;
            int j = j0 + jl;
            float i0 = inv[jl], i1 = inv[jl + 1];
            int idx0 = c0r * 1024 + j, idx1 = (c0r + 8) * 1024 + j;
            float2 q0 = *(const float2*)&Qr[idx0];
            float2 q1 = *(const float2*)&Qr[idx1];
            float2 w0 = *(const float2*)&ln1w[idx0];
            float2 w1 = *(const float2*)&ln1w[idx1];
            float2 b0 = *(const float2*)&ln1b[idx0];
            float2 b1 = *(const float2*)&ln1b[idx1];
            float qn00 = (q0.x - mu) * rstd * w0.x + b0.x;
            float qn01 = (q0.y - mu) * rstd * w0.y + b0.y;
            float qn10 = (q1.x - mu) * rstd * w1.x + b1.x;
            float qn11 = (q1.y - mu) * rstd * w1.y + b1.y;
            float2 o0 = make_float2(oacc[mt][nt][0] * i0 + qn00,
                                    oacc[mt][nt][1] * i1 + qn01);
            float2 o1 = make_float2(oacc[mt][nt][2] * i0 + qn10,
                                    oacc[mt][nt][3] * i1 + qn11);
            *(float2*)&outp[idx0] = o0;
            *(float2*)&outp[idx1] = o1;
        }
    }
}

// ---------------------------------------------------------------------------
extern "C" void kernel_launch(void* const* d_in, const int* in_sizes, int n_in,
                              void* d_out, int out_size)
{
    const float* q    = (const float*)d_in[0];
    const float* k    = (const float*)d_in[1];
    const float* v    = (const float*)d_in[2];
    const float* ln1w = (const float*)d_in[3];
    const float* ln1b = (const float*)d_in[4];
    const float* ln2w = (const float*)d_in[5];
    const float* ln2b = (const float*)d_in[6];
    const float* ln3w = (const float*)d_in[7];
    const float* ln3b = (const float*)d_in[8];
    const float* wq   = (const float*)d_in[9];
    const float* bq   = (const float*)d_in[10];
    const float* wk   = (const float*)d_in[11];
    const float* bk   = (const float*)d_in[12];
    const float* wv   = (const float*)d_in[13];
    const float* bv   = (const float*)d_in[14];
    float* out = (float*)d_out;

    static bool attr_set = false;
    if (!attr_set) {
        cudaFuncSetAttribute(fused_attn_kernel,
                             cudaFuncAttributeMaxDynamicSharedMemorySize,
                             (int)FUSED_SMEM);
        attr_set = true;
    }

    ln_part_kernel<<<dim3(64, 3, 4), 256>>>(q, k, v);
    ln_finalize_kernel<<<1, 192>>>();
    conv_mma_kernel<<<dim3(8, 1, 192), 256>>>(q, k, v,
                                              ln1w, ln1b, ln2w, ln2b, ln3w, ln3b,
                                              wq, bq, wk, bk, wv, bv);
    fused_attn_kernel<<<dim3(8, 64), 256, FUSED_SMEM>>>(out, q, ln1w, ln1b);
}

// round 8
// speedup vs baseline: 1.0356x; 1.0356x over previous
#include <cuda_runtime.h>
#include <cuda_fp16.h>
#include <cstdint>

#define NB 64
#define CCH 128
#define HW 1024
#define PER_N (CCH*HW)          // 131072
#define PER_T (NB*PER_N)        // 8388608
#define S_SCALE 0.08838834764831845f   // 1/sqrt(128)

// Scratch (device globals: allocation-free per harness rules)
__device__ __half g_projh[3u*PER_T];   // Q_T [n][j][c], K_T(scaled) [n][i][c], V [n][c][i]
__device__ float2 g_stats[3*NB];       // (mu, rstd) per (t, n)
__device__ float2 g_part[3*NB*4];      // partial (sum, sumsq)

// ---------------------------------------------------------------------------
// helpers
// ---------------------------------------------------------------------------
__device__ __forceinline__ uint32_t f2tf32(float x) {
    uint32_t u; asm("cvt.rna.tf32.f32 %0, %1;" : "=r"(u) : "f"(x)); return u;
}
__device__ __forceinline__ void mma_tf32(float c[4],
    uint32_t a0, uint32_t a1, uint32_t a2, uint32_t a3, uint32_t b0, uint32_t b1)
{
    asm volatile(
        "mma.sync.aligned.m16n8k8.row.col.f32.tf32.tf32.f32 "
        "{%0,%1,%2,%3},{%4,%5,%6,%7},{%8,%9},{%0,%1,%2,%3};"
        : "+f"(c[0]), "+f"(c[1]), "+f"(c[2]), "+f"(c[3])
        : "r"(a0), "r"(a1), "r"(a2), "r"(a3), "r"(b0), "r"(b1));
}
__device__ __forceinline__ void mma_f16(float c[4],
    uint32_t a0, uint32_t a1, uint32_t a2, uint32_t a3, uint32_t b0, uint32_t b1)
{
    asm volatile(
        "mma.sync.aligned.m16n8k16.row.col.f32.f16.f16.f32 "
        "{%0,%1,%2,%3},{%4,%5,%6,%7},{%8,%9},{%0,%1,%2,%3};"
        : "+f"(c[0]), "+f"(c[1]), "+f"(c[2]), "+f"(c[3])
        : "r"(a0), "r"(a1), "r"(a2), "r"(a3), "r"(b0), "r"(b1));
}
__device__ __forceinline__ void ldsm_x4(uint32_t r[4], uint32_t addr) {
    asm volatile("ldmatrix.sync.aligned.m8n8.x4.shared.b16 {%0,%1,%2,%3}, [%4];"
        : "=r"(r[0]), "=r"(r[1]), "=r"(r[2]), "=r"(r[3]) : "r"(addr));
}
__device__ __forceinline__ void stsm_x2_t(uint32_t addr, uint32_t r0, uint32_t r1) {
    asm volatile("stmatrix.sync.aligned.m8n8.x2.trans.shared.b16 [%0], {%1,%2};"
        :: "r"(addr), "r"(r0), "r"(r1) : "memory");
}
__device__ __forceinline__ void cp16(uint32_t dst_smem, const void* src) {
    asm volatile("cp.async.ca.shared.global [%0], [%1], 16;"
                 :: "r"(dst_smem), "l"(src) : "memory");
}
__device__ __forceinline__ void cp_commit() {
    asm volatile("cp.async.commit_group;" ::: "memory");
}
__device__ __forceinline__ void cp_wait0() {
    asm volatile("cp.async.wait_group 0;" ::: "memory");
}

// ---------------------------------------------------------------------------
// LN partial sums: grid (64, 3, 4), 256 threads
// ---------------------------------------------------------------------------
__global__ __launch_bounds__(256) void ln_part_kernel(
    const float* __restrict__ q, const float* __restrict__ k, const float* __restrict__ v)
{
    int n = blockIdx.x, t = blockIdx.y, p = blockIdx.z;
    const float* x = (t == 0) ? q : (t == 1) ? k : v;
    const float4* x4 = reinterpret_cast<const float4*>(x + (size_t)n * PER_N) + p * (PER_N / 16);

    float s = 0.f, ss = 0.f;
    for (int i = threadIdx.x; i < PER_N / 16; i += 256) {
        float4 u = x4[i];
        s  += u.x + u.y + u.z + u.w;
        ss += u.x * u.x + u.y * u.y + u.z * u.z + u.w * u.w;
    }
    __shared__ float sh_s[8], sh_ss[8];
    for (int off = 16; off > 0; off >>= 1) {
        s  += __shfl_down_sync(0xffffffffu, s, off);
        ss += __shfl_down_sync(0xffffffffu, ss, off);
    }
    int warp = threadIdx.x >> 5, lane = threadIdx.x & 31;
    if (lane == 0) { sh_s[warp] = s; sh_ss[warp] = ss; }
    __syncthreads();
    if (warp == 0) {
        s  = (lane < 8) ? sh_s[lane]  : 0.f;
        ss = (lane < 8) ? sh_ss[lane] : 0.f;
        for (int off = 4; off > 0; off >>= 1) {
            s  += __shfl_down_sync(0xffffffffu, s, off);
            ss += __shfl_down_sync(0xffffffffu, ss, off);
        }
        if (lane == 0) g_part[(t * NB + n) * 4 + p] = make_float2(s, ss);
    }
}

__global__ void ln_finalize_kernel()
{
    int i = threadIdx.x;
    if (i < 3 * NB) {
        float s = 0.f, ss = 0.f;
#pragma unroll
        for (int p = 0; p < 4; p++) {
            float2 u = g_part[i * 4 + p];
            s += u.x; ss += u.y;
        }
        float mu  = s * (1.f / (float)PER_N);
        float var = ss * (1.f / (float)PER_N) - mu * mu;
        g_stats[i] = make_float2(mu, rsqrtf(var + 1e-5f));
    }
}

// ---------------------------------------------------------------------------
// conv 1x1 via tf32 mma with LN fused into B staging (unchanged from R7)
// ---------------------------------------------------------------------------
__global__ __launch_bounds__(256) void conv_mma_kernel(
    const float* __restrict__ q, const float* __restrict__ k, const float* __restrict__ v,
    const float* __restrict__ ln1w, const float* __restrict__ ln1b,
    const float* __restrict__ ln2w, const float* __restrict__ ln2b,
    const float* __restrict__ ln3w, const float* __restrict__ ln3b,
    const float* __restrict__ wq, const float* __restrict__ bq,
    const float* __restrict__ wk, const float* __restrict__ bk,
    const float* __restrict__ wv, const float* __restrict__ bv)
{
    int t = blockIdx.z >> 6, n = blockIdx.z & 63;
    const float* W  = (t == 0) ? wq : (t == 1) ? wk : wv;
    const float* Bi = (t == 0) ? bq : (t == 1) ? bk : bv;
    const float* Xr = ((t == 0) ? q : (t == 1) ? k : v) + (size_t)n * PER_N;
    const float* LW = (t == 0) ? ln1w : (t == 1) ? ln2w : ln3w;
    const float* LB = (t == 0) ? ln1b : (t == 1) ? ln2b : ln3b;
    float2 st = g_stats[t * NB + n];
    float mu = st.x, rstd = st.y;
    int j0 = blockIdx.x * 128;

    __shared__ union {
        struct { uint32_t As[128][36]; uint32_t Bs[32][136]; } s;
        __half ep[128][136];
    } u;

    int tid = threadIdx.x, lane = tid & 31, warp = tid >> 5;
    int g = lane >> 2, t4 = lane & 3;
    int wm = (warp >> 2) * 64, wn = (warp & 3) * 32;

    float acc[4][4][4];
#pragma unroll
    for (int a = 0; a < 4; a++)
#pragma unroll
        for (int b2 = 0; b2 < 4; b2++)
#pragma unroll
            for (int e = 0; e < 4; e++) acc[a][b2][e] = 0.f;

    for (int k0 = 0; k0 < 128; k0 += 32) {
#pragma unroll
        for (int r = 0; r < 4; r++) {
            int lin = tid + r * 256;
            int m = lin >> 3, k4 = lin & 7;
            float4 vv = *(const float4*)&W[m * 128 + k0 + k4 * 4];
            uint4 uu = make_uint4(f2tf32(vv.x), f2tf32(vv.y), f2tf32(vv.z), f2tf32(vv.w));
            *(uint4*)&u.s.As[m][k4 * 4] = uu;
        }
#pragma unroll
        for (int r = 0; r < 4; r++) {
            int lin = tid + r * 256;
            int row = lin >> 5, c4 = lin & 31;
            int idx = (k0 + row) * 1024 + j0 + c4 * 4;
            float4 xv = *(const float4*)&Xr[idx];
            float4 lw = *(const float4*)&LW[idx];
            float4 lb = *(const float4*)&LB[idx];
            float n0 = (xv.x - mu) * rstd * lw.x + lb.x;
            float n1 = (xv.y - mu) * rstd * lw.y + lb.y;
            float n2 = (xv.z - mu) * rstd * lw.z + lb.z;
            float n3 = (xv.w - mu) * rstd * lw.w + lb.w;
            uint4 uu = make_uint4(f2tf32(n0), f2tf32(n1), f2tf32(n2), f2tf32(n3));
            *(uint4*)&u.s.Bs[row][c4 * 4] = uu;
        }
        __syncthreads();
#pragma unroll
        for (int ks = 0; ks < 4; ks++) {
            int kl = ks * 8 + t4, kh = kl + 4;
            uint32_t af[4][4], bf[4][2];
#pragma unroll
            for (int mt = 0; mt < 4; mt++) {
                int mb = wm + mt * 16 + g;
                af[mt][0] = u.s.As[mb][kl];     af[mt][1] = u.s.As[mb + 8][kl];
                af[mt][2] = u.s.As[mb][kh];     af[mt][3] = u.s.As[mb + 8][kh];
            }
#pragma unroll
            for (int nt = 0; nt < 4; nt++) {
                int nb = wn + nt * 8 + g;
                bf[nt][0] = u.s.Bs[kl][nb];     bf[nt][1] = u.s.Bs[kh][nb];
            }
#pragma unroll
            for (int mt = 0; mt < 4; mt++)
#pragma unroll
                for (int nt = 0; nt < 4; nt++)
                    mma_tf32(acc[mt][nt], af[mt][0], af[mt][1], af[mt][2], af[mt][3],
                             bf[nt][0], bf[nt][1]);
        }
        __syncthreads();
    }

    float sc = (t == 1) ? S_SCALE : 1.f;
#pragma unroll
    for (int mt = 0; mt < 4; mt++) {
        int m0 = wm + mt * 16 + g;
        float bias0 = Bi[m0], bias1 = Bi[m0 + 8];
#pragma unroll
        for (int nt = 0; nt < 4; nt++) {
            int jl = wn + nt * 8 + t4 * 2;
            float v0 = (acc[mt][nt][0] + bias0) * sc;
            float v1 = (acc[mt][nt][1] + bias0) * sc;
            float v2 = (acc[mt][nt][2] + bias1) * sc;
            float v3 = (acc[mt][nt][3] + bias1) * sc;
            if (t < 2) {
                u.ep[jl][m0]         = __float2half(v0);
                u.ep[jl + 1][m0]     = __float2half(v1);
                u.ep[jl][m0 + 8]     = __float2half(v2);
                u.ep[jl + 1][m0 + 8] = __float2half(v3);
            } else {
                u.ep[m0][jl]         = __float2half(v0);
                u.ep[m0][jl + 1]     = __float2half(v1);
                u.ep[m0 + 8][jl]     = __float2half(v2);
                u.ep[m0 + 8][jl + 1] = __float2half(v3);
            }
        }
    }
    __syncthreads();

    __half* dst = g_projh + (size_t)t * PER_T + (size_t)n * PER_N;
    if (t < 2) {
#pragma unroll
        for (int r = 0; r < 8; r++) {
            int lin = tid + r * 256;
            int row = lin >> 4, off = lin & 15;
            *(uint4*)&dst[(size_t)(j0 + row) * 128 + off * 8] = *(uint4*)&u.ep[row][off * 8];
        }
    } else {
#pragma unroll
        for (int r = 0; r < 8; r++) {
            int lin = tid + r * 256;
            int row = lin >> 4, off = lin & 15;
            *(uint4*)&dst[(size_t)row * 1024 + j0 + off * 8] = *(uint4*)&u.ep[row][off * 8];
        }
    }
}

// ---------------------------------------------------------------------------
// Fused attention, 512 threads (16 warps, 4x4 warp grid, 32x32 warp tiles).
// grid (8, 64)
// ---------------------------------------------------------------------------
#define TS 136                      // smem row stride (halfs)
#define TILE_H (128 * TS)           // halfs per 128-row tile
#define FUSED_SMEM (( (size_t)6 * TILE_H ) * 2 + 4*128*4 + 128*4)

__global__ __launch_bounds__(512, 1) void fused_attn_kernel(
    float* __restrict__ out,
    const float* __restrict__ qraw,
    const float* __restrict__ ln1w, const float* __restrict__ ln1b)
{
    extern __shared__ __align__(16) char smem_raw[];
    __half* Qs = (__half*)smem_raw;        // [128][TS]
    __half* Ks = Qs + TILE_H;              // [2][128][TS]
    __half* Vs = Ks + 2 * TILE_H;          // [2][128][TS]
    __half* Et = Vs + 2 * TILE_H;          // [128][TS]  (E transposed: [j][i])
    float*  red = (float*)(Et + TILE_H);   // [4][128]
    float*  inv = red + 4 * 128;           // [128]

    int n = blockIdx.y, j0 = blockIdx.x * 128;
    const __half* Qh = g_projh + (size_t)n * PER_N;                // [j][c]
    const __half* Kh = g_projh + PER_T + (size_t)n * PER_N;        // [i][c] (scaled)
    const __half* Vh = g_projh + 2u * PER_T + (size_t)n * PER_N;   // [c][i]
    const float*  Qr = qraw + (size_t)n * PER_N;
    float2 st = g_stats[n];
    float mu = st.x, rstd = st.y;

    int tid = threadIdx.x, lane = tid & 31, warp = tid >> 5;
    int g = lane >> 2, t4 = lane & 3;
    int wi = warp >> 2, wj = warp & 3;     // 4x4 warp grid, 32x32 tiles

    int rL = lane & 15, cL = (lane >> 4) * 8;   // ldmatrix addressing
    int rS = lane & 7,  hS = (lane >> 3) & 1;   // stmatrix addressing (lanes 0-15)

    uint32_t qs_b = (uint32_t)__cvta_generic_to_shared(Qs);
    uint32_t ks_b = (uint32_t)__cvta_generic_to_shared(Ks);
    uint32_t vs_b = (uint32_t)__cvta_generic_to_shared(Vs);
    uint32_t et_b = (uint32_t)__cvta_generic_to_shared(Et);

    // prefetch Q + K0 + V0 (512 threads: 4 chunks each per tile)
#pragma unroll
    for (int r = 0; r < 4; r++) {
        int lin = tid + r * 512;
        int row = lin >> 4, off = lin & 15;
        uint32_t so = (uint32_t)(row * TS + off * 8) * 2u;
        cp16(qs_b + so, Qh + (size_t)(j0 + row) * 128 + off * 8);
        cp16(ks_b + so, Kh + (size_t)row * 128 + off * 8);
        cp16(vs_b + so, Vh + (size_t)row * 1024 + off * 8);
    }
    cp_commit();

    float oacc[2][4][4];
#pragma unroll
    for (int a = 0; a < 2; a++)
#pragma unroll
        for (int b2 = 0; b2 < 4; b2++)
#pragma unroll
            for (int e = 0; e < 4; e++) oacc[a][b2][e] = 0.f;
    float psum[4][2];
#pragma unroll
    for (int a = 0; a < 4; a++) { psum[a][0] = 0.f; psum[a][1] = 0.f; }

    cp_wait0();
    __syncthreads();

    for (int it = 0; it < 8; it++) {
        int buf = it & 1, nbuf = buf ^ 1;
        if (it < 7) {
#pragma unroll
            for (int r = 0; r < 4; r++) {
                int lin = tid + r * 512;
                int row = lin >> 4, off = lin & 15;
                uint32_t so = (uint32_t)(nbuf * TILE_H + row * TS + off * 8) * 2u;
                cp16(ks_b + so, Kh + (size_t)((it + 1) * 128 + row) * 128 + off * 8);
                cp16(vs_b + so, Vh + (size_t)row * 1024 + (it + 1) * 128 + off * 8);
            }
            cp_commit();
        }

        // ---- MMA1: S (32x32 per warp) over k=c=128 ----
        uint32_t kbuf = ks_b + (uint32_t)(buf * TILE_H) * 2u;
        float sacc[2][4][4];
#pragma unroll
        for (int a = 0; a < 2; a++)
#pragma unroll
            for (int b2 = 0; b2 < 4; b2++)
#pragma unroll
                for (int e = 0; e < 4; e++) sacc[a][b2][e] = 0.f;

#pragma unroll
        for (int kk = 0; kk < 8; kk++) {
            int kb0 = kk * 16 + cL;
            uint32_t a[2][4], b[2][4];
#pragma unroll
            for (int mt = 0; mt < 2; mt++)
                ldsm_x4(a[mt], kbuf + (uint32_t)((wi * 32 + mt * 16 + rL) * TS + kb0) * 2u);
#pragma unroll
            for (int np = 0; np < 2; np++)
                ldsm_x4(b[np], qs_b + (uint32_t)((wj * 32 + np * 16 + rL) * TS + kb0) * 2u);
#pragma unroll
            for (int mt = 0; mt < 2; mt++)
#pragma unroll
                for (int np = 0; np < 2; np++) {
                    mma_f16(sacc[mt][np * 2],     a[mt][0], a[mt][1], a[mt][2], a[mt][3],
                            b[np][0], b[np][2]);
                    mma_f16(sacc[mt][np * 2 + 1], a[mt][0], a[mt][1], a[mt][2], a[mt][3],
                            b[np][1], b[np][3]);
                }
        }

        // ---- exp + column partial sums + E^T via stmatrix.trans ----
#pragma unroll
        for (int mt = 0; mt < 2; mt++) {
            int ib = wi * 32 + mt * 16;
#pragma unroll
            for (int nt = 0; nt < 4; nt++) {
                int jb = wj * 32 + nt * 8;
                float e0 = __expf(fminf(sacc[mt][nt][0], 11.f));
                float e1 = __expf(fminf(sacc[mt][nt][1], 11.f));
                float e2 = __expf(fminf(sacc[mt][nt][2], 11.f));
                float e3 = __expf(fminf(sacc[mt][nt][3], 11.f));
                psum[nt][0] += e0 + e2;
                psum[nt][1] += e1 + e3;
                __half2 h01 = __floats2half2_rn(e0, e1);
                __half2 h23 = __floats2half2_rn(e2, e3);
                uint32_t addr = et_b +
                    (uint32_t)((jb + rS) * TS + ib + hS * 8) * 2u;
                stsm_x2_t(addr, *(uint32_t*)&h01, *(uint32_t*)&h23);
            }
        }
        __syncthreads();

        // ---- MMA2: oacc += V @ E ----
        uint32_t vbuf = vs_b + (uint32_t)(buf * TILE_H) * 2u;
#pragma unroll
        for (int kk = 0; kk < 8; kk++) {
            int kb0 = kk * 16 + cL;
            uint32_t a[2][4], b[2][4];
#pragma unroll
            for (int mt = 0; mt < 2; mt++)
                ldsm_x4(a[mt], vbuf + (uint32_t)((wi * 32 + mt * 16 + rL) * TS + kb0) * 2u);
#pragma unroll
            for (int np = 0; np < 2; np++)
                ldsm_x4(b[np], et_b + (uint32_t)((wj * 32 + np * 16 + rL) * TS + kb0) * 2u);
#pragma unroll
            for (int mt = 0; mt < 2; mt++)
#pragma unroll
                for (int np = 0; np < 2; np++) {
                    mma_f16(oacc[mt][np * 2],     a[mt][0], a[mt][1], a[mt][2], a[mt][3],
                            b[np][0], b[np][2]);
                    mma_f16(oacc[mt][np * 2 + 1], a[mt][0], a[mt][1], a[mt][2], a[mt][3],
                            b[np][1], b[np][3]);
                }
        }

        if (it < 7) cp_wait0();
        __syncthreads();
    }

    // ---- column-sum reduce: shfl over g, smem over wi ----
#pragma unroll
    for (int nt = 0; nt < 4; nt++) {
#pragma unroll
        for (int e = 0; e < 2; e++) {
            float v = psum[nt][e];
            v += __shfl_down_sync(0xffffffffu, v, 16);
            v += __shfl_down_sync(0xffffffffu, v, 8);
            v += __shfl_down_sync(0xffffffffu, v, 4);
            if (lane < 4)
                red[wi * 128 + wj * 32 + nt * 8 + lane * 2 + e] = v;
        }
    }
    __syncthreads();
    if (tid < 128)
        inv[tid] = 1.f / (red[tid] + red[128 + tid] + red[256 + tid] + red[384 + tid]);
    __syncthreads();

    // ---- epilogue: normalize + residual (qn recomputed from raw q) ----
    float* outp = out + (size_t)n * PER_N;
#pragma unroll
    for (int mt = 0; mt < 2; mt++) {
        int c0r = wi * 32 + mt * 16 + g;
#pragma unroll
        for (int nt = 0; nt < 4; nt++) {
            int jl = wj * 32 + nt * 8 + t4 * 2;
            int j = j0 + jl;
            float i0 = inv[jl], i1 = inv[jl + 1];
            int idx0 = c0r * 1024 + j, idx1 = (c0r + 8) * 1024 + j;
            float2 q0 = *(const float2*)&Qr[idx0];
            float2 q1 = *(const float2*)&Qr[idx1];
            float2 w0 = *(const float2*)&ln1w[idx0];
            float2 w1 = *(const float2*)&ln1w[idx1];
            float2 b0 = *(const float2*)&ln1b[idx0];
            float2 b1 = *(const float2*)&ln1b[idx1];
            float qn00 = (q0.x - mu) * rstd * w0.x + b0.x;
            float qn01 = (q0.y - mu) * rstd * w0.y + b0.y;
            float qn10 = (q1.x - mu) * rstd * w1.x + b1.x;
            float qn11 = (q1.y - mu) * rstd * w1.y + b1.y;
            float2 o0 = make_float2(oacc[mt][nt][0] * i0 + qn00,
                                    oacc[mt][nt][1] * i1 + qn01);
            float2 o1 = make_float2(oacc[mt][nt][2] * i0 + qn10,
                                    oacc[mt][nt][3] * i1 + qn11);
            *(float2*)&outp[idx0] = o0;
            *(float2*)&outp[idx1] = o1;
        }
    }
}

// ---------------------------------------------------------------------------
extern "C" void kernel_launch(void* const* d_in, const int* in_sizes, int n_in,
                              void* d_out, int out_size)
{
    const float* q    = (const float*)d_in[0];
    const float* k    = (const float*)d_in[1];
    const float* v    = (const float*)d_in[2];
    const float* ln1w = (const float*)d_in[3];
    const float* ln1b = (const float*)d_in[4];
    const float* ln2w = (const float*)d_in[5];
    const float* ln2b = (const float*)d_in[6];
    const float* ln3w = (const float*)d_in[7];
    const float* ln3b = (const float*)d_in[8];
    const float* wq   = (const float*)d_in[9];
    const float* bq   = (const float*)d_in[10];
    const float* wk   = (const float*)d_in[11];
    const float* bk   = (const float*)d_in[12];
    const float* wv   = (const float*)d_in[13];
    const float* bv   = (const float*)d_in[14];
    float* out = (float*)d_out;

    static bool attr_set = false;
    if (!attr_set) {
        cudaFuncSetAttribute(fused_attn_kernel,
                             cudaFuncAttributeMaxDynamicSharedMemorySize,
                             (int)FUSED_SMEM);
        attr_set = true;
    }

    ln_part_kernel<<<dim3(64, 3, 4), 256>>>(q, k, v);
    ln_finalize_kernel<<<1, 192>>>();
    conv_mma_kernel<<<dim3(8, 1, 192), 256>>>(q, k, v,
                                              ln1w, ln1b, ln2w, ln2b, ln3w, ln3b,
                                              wq, bq, wk, bk, wv, bv);
    fused_attn_kernel<<<dim3(8, 64), 512, FUSED_SMEM>>>(out, q, ln1w, ln1b);
}

// round 9
// speedup vs baseline: 1.0922x; 1.0546x over previous
#include <cuda_runtime.h>
#include <cuda_fp16.h>
#include <cstdint>

#define NB 64
#define CCH 128
#define HW 1024
#define PER_N (CCH*HW)          // 131072
#define PER_T (NB*PER_N)        // 8388608
#define S_SCALE 0.08838834764831845f   // 1/sqrt(128)

// Scratch (device globals: allocation-free per harness rules)
__device__ __half g_projh[3u*PER_T];   // Q_T [n][j][c], K_T(scaled) [n][i][c], V [n][c][i]
__device__ float2 g_stats[3*NB];       // (mu, rstd) per (t, n)
__device__ float2 g_part[3*NB*4];      // partial (sum, sumsq)

// ---------------------------------------------------------------------------
// helpers
// ---------------------------------------------------------------------------
__device__ __forceinline__ uint32_t f2tf32(float x) {
    uint32_t u; asm("cvt.rna.tf32.f32 %0, %1;" : "=r"(u) : "f"(x)); return u;
}
__device__ __forceinline__ void mma_tf32(float c[4],
    uint32_t a0, uint32_t a1, uint32_t a2, uint32_t a3, uint32_t b0, uint32_t b1)
{
    asm volatile(
        "mma.sync.aligned.m16n8k8.row.col.f32.tf32.tf32.f32 "
        "{%0,%1,%2,%3},{%4,%5,%6,%7},{%8,%9},{%0,%1,%2,%3};"
        : "+f"(c[0]), "+f"(c[1]), "+f"(c[2]), "+f"(c[3])
        : "r"(a0), "r"(a1), "r"(a2), "r"(a3), "r"(b0), "r"(b1));
}
__device__ __forceinline__ void mma_f16(float c[4],
    uint32_t a0, uint32_t a1, uint32_t a2, uint32_t a3, uint32_t b0, uint32_t b1)
{
    asm volatile(
        "mma.sync.aligned.m16n8k16.row.col.f32.f16.f16.f32 "
        "{%0,%1,%2,%3},{%4,%5,%6,%7},{%8,%9},{%0,%1,%2,%3};"
        : "+f"(c[0]), "+f"(c[1]), "+f"(c[2]), "+f"(c[3])
        : "r"(a0), "r"(a1), "r"(a2), "r"(a3), "r"(b0), "r"(b1));
}
__device__ __forceinline__ void ldsm_x4(uint32_t r[4], uint32_t addr) {
    asm volatile("ldmatrix.sync.aligned.m8n8.x4.shared.b16 {%0,%1,%2,%3}, [%4];"
        : "=r"(r[0]), "=r"(r[1]), "=r"(r[2]), "=r"(r[3]) : "r"(addr));
}
__device__ __forceinline__ void cp16(uint32_t dst_smem, const void* src) {
    asm volatile("cp.async.ca.shared.global [%0], [%1], 16;"
                 :: "r"(dst_smem), "l"(src) : "memory");
}
__device__ __forceinline__ void cp_commit() {
    asm volatile("cp.async.commit_group;" ::: "memory");
}
__device__ __forceinline__ void cp_wait0() {
    asm volatile("cp.async.wait_group 0;" ::: "memory");
}

// ---------------------------------------------------------------------------
// LN partial sums: grid (64, 3, 4), 256 threads
// ---------------------------------------------------------------------------
__global__ __launch_bounds__(256) void ln_part_kernel(
    const float* __restrict__ q, const float* __restrict__ k, const float* __restrict__ v)
{
    int n = blockIdx.x, t = blockIdx.y, p = blockIdx.z;
    const float* x = (t == 0) ? q : (t == 1) ? k : v;
    const float4* x4 = reinterpret_cast<const float4*>(x + (size_t)n * PER_N) + p * (PER_N / 16);

    float s = 0.f, ss = 0.f;
    for (int i = threadIdx.x; i < PER_N / 16; i += 256) {
        float4 u = x4[i];
        s  += u.x + u.y + u.z + u.w;
        ss += u.x * u.x + u.y * u.y + u.z * u.z + u.w * u.w;
    }
    __shared__ float sh_s[8], sh_ss[8];
    for (int off = 16; off > 0; off >>= 1) {
        s  += __shfl_down_sync(0xffffffffu, s, off);
        ss += __shfl_down_sync(0xffffffffu, ss, off);
    }
    int warp = threadIdx.x >> 5, lane = threadIdx.x & 31;
    if (lane == 0) { sh_s[warp] = s; sh_ss[warp] = ss; }
    __syncthreads();
    if (warp == 0) {
        s  = (lane < 8) ? sh_s[lane]  : 0.f;
        ss = (lane < 8) ? sh_ss[lane] : 0.f;
        for (int off = 4; off > 0; off >>= 1) {
            s  += __shfl_down_sync(0xffffffffu, s, off);
            ss += __shfl_down_sync(0xffffffffu, ss, off);
        }
        if (lane == 0) g_part[(t * NB + n) * 4 + p] = make_float2(s, ss);
    }
}

__global__ void ln_finalize_kernel()
{
    int i = threadIdx.x;
    if (i < 3 * NB) {
        float s = 0.f, ss = 0.f;
#pragma unroll
        for (int p = 0; p < 4; p++) {
            float2 u = g_part[i * 4 + p];
            s += u.x; ss += u.y;
        }
        float mu  = s * (1.f / (float)PER_N);
        float var = ss * (1.f / (float)PER_N) - mu * mu;
        g_stats[i] = make_float2(mu, rsqrtf(var + 1e-5f));
    }
}

// ---------------------------------------------------------------------------
// conv 1x1 via tf32 mma with LN fused into B staging (unchanged)
// ---------------------------------------------------------------------------
__global__ __launch_bounds__(256) void conv_mma_kernel(
    const float* __restrict__ q, const float* __restrict__ k, const float* __restrict__ v,
    const float* __restrict__ ln1w, const float* __restrict__ ln1b,
    const float* __restrict__ ln2w, const float* __restrict__ ln2b,
    const float* __restrict__ ln3w, const float* __restrict__ ln3b,
    const float* __restrict__ wq, const float* __restrict__ bq,
    const float* __restrict__ wk, const float* __restrict__ bk,
    const float* __restrict__ wv, const float* __restrict__ bv)
{
    int t = blockIdx.z >> 6, n = blockIdx.z & 63;
    const float* W  = (t == 0) ? wq : (t == 1) ? wk : wv;
    const float* Bi = (t == 0) ? bq : (t == 1) ? bk : bv;
    const float* Xr = ((t == 0) ? q : (t == 1) ? k : v) + (size_t)n * PER_N;
    const float* LW = (t == 0) ? ln1w : (t == 1) ? ln2w : ln3w;
    const float* LB = (t == 0) ? ln1b : (t == 1) ? ln2b : ln3b;
    float2 st = g_stats[t * NB + n];
    float mu = st.x, rstd = st.y;
    int j0 = blockIdx.x * 128;

    __shared__ union {
        struct { uint32_t As[128][36]; uint32_t Bs[32][136]; } s;
        __half ep[128][136];
    } u;

    int tid = threadIdx.x, lane = tid & 31, warp = tid >> 5;
    int g = lane >> 2, t4 = lane & 3;
    int wm = (warp >> 2) * 64, wn = (warp & 3) * 32;

    float acc[4][4][4];
#pragma unroll
    for (int a = 0; a < 4; a++)
#pragma unroll
        for (int b2 = 0; b2 < 4; b2++)
#pragma unroll
            for (int e = 0; e < 4; e++) acc[a][b2][e] = 0.f;

    for (int k0 = 0; k0 < 128; k0 += 32) {
#pragma unroll
        for (int r = 0; r < 4; r++) {
            int lin = tid + r * 256;
            int m = lin >> 3, k4 = lin & 7;
            float4 vv = *(const float4*)&W[m * 128 + k0 + k4 * 4];
            uint4 uu = make_uint4(f2tf32(vv.x), f2tf32(vv.y), f2tf32(vv.z), f2tf32(vv.w));
            *(uint4*)&u.s.As[m][k4 * 4] = uu;
        }
#pragma unroll
        for (int r = 0; r < 4; r++) {
            int lin = tid + r * 256;
            int row = lin >> 5, c4 = lin & 31;
            int idx = (k0 + row) * 1024 + j0 + c4 * 4;
            float4 xv = *(const float4*)&Xr[idx];
            float4 lw = *(const float4*)&LW[idx];
            float4 lb = *(const float4*)&LB[idx];
            float n0 = (xv.x - mu) * rstd * lw.x + lb.x;
            float n1 = (xv.y - mu) * rstd * lw.y + lb.y;
            float n2 = (xv.z - mu) * rstd * lw.z + lb.z;
            float n3 = (xv.w - mu) * rstd * lw.w + lb.w;
            uint4 uu = make_uint4(f2tf32(n0), f2tf32(n1), f2tf32(n2), f2tf32(n3));
            *(uint4*)&u.s.Bs[row][c4 * 4] = uu;
        }
        __syncthreads();
#pragma unroll
        for (int ks = 0; ks < 4; ks++) {
            int kl = ks * 8 + t4, kh = kl + 4;
            uint32_t af[4][4], bf[4][2];
#pragma unroll
            for (int mt = 0; mt < 4; mt++) {
                int mb = wm + mt * 16 + g;
                af[mt][0] = u.s.As[mb][kl];     af[mt][1] = u.s.As[mb + 8][kl];
                af[mt][2] = u.s.As[mb][kh];     af[mt][3] = u.s.As[mb + 8][kh];
            }
#pragma unroll
            for (int nt = 0; nt < 4; nt++) {
                int nb = wn + nt * 8 + g;
                bf[nt][0] = u.s.Bs[kl][nb];     bf[nt][1] = u.s.Bs[kh][nb];
            }
#pragma unroll
            for (int mt = 0; mt < 4; mt++)
#pragma unroll
                for (int nt = 0; nt < 4; nt++)
                    mma_tf32(acc[mt][nt], af[mt][0], af[mt][1], af[mt][2], af[mt][3],
                             bf[nt][0], bf[nt][1]);
        }
        __syncthreads();
    }

    float sc = (t == 1) ? S_SCALE : 1.f;
#pragma unroll
    for (int mt = 0; mt < 4; mt++) {
        int m0 = wm + mt * 16 + g;
        float bias0 = Bi[m0], bias1 = Bi[m0 + 8];
#pragma unroll
        for (int nt = 0; nt < 4; nt++) {
            int jl = wn + nt * 8 + t4 * 2;
            float v0 = (acc[mt][nt][0] + bias0) * sc;
            float v1 = (acc[mt][nt][1] + bias0) * sc;
            float v2 = (acc[mt][nt][2] + bias1) * sc;
            float v3 = (acc[mt][nt][3] + bias1) * sc;
            if (t < 2) {
                u.ep[jl][m0]         = __float2half(v0);
                u.ep[jl + 1][m0]     = __float2half(v1);
                u.ep[jl][m0 + 8]     = __float2half(v2);
                u.ep[jl + 1][m0 + 8] = __float2half(v3);
            } else {
                u.ep[m0][jl]         = __float2half(v0);
                u.ep[m0][jl + 1]     = __float2half(v1);
                u.ep[m0 + 8][jl]     = __float2half(v2);
                u.ep[m0 + 8][jl + 1] = __float2half(v3);
            }
        }
    }
    __syncthreads();

    __half* dst = g_projh + (size_t)t * PER_T + (size_t)n * PER_N;
    if (t < 2) {
#pragma unroll
        for (int r = 0; r < 8; r++) {
            int lin = tid + r * 256;
            int row = lin >> 4, off = lin & 15;
            *(uint4*)&dst[(size_t)(j0 + row) * 128 + off * 8] = *(uint4*)&u.ep[row][off * 8];
        }
    } else {
#pragma unroll
        for (int r = 0; r < 8; r++) {
            int lin = tid + r * 256;
            int row = lin >> 4, off = lin & 15;
            *(uint4*)&dst[(size_t)row * 1024 + j0 + off * 8] = *(uint4*)&u.ep[row][off * 8];
        }
    }
}

// ---------------------------------------------------------------------------
// Fused attention, FA2-style register-resident P.
// 256 threads / 8 warps; warp w owns j rows [w*16, w*16+16).
//   S^T[j,i] = Q[j,c] K[i,c]   (A=Q cached in regs, B=K)
//   P = exp(S^T) stays in registers -> A operand of
//   out^T[j,c] += P[j,i] V^T[i,c] (B = V[c][i] tile)
// One barrier per key tile. Denominator fully intra-warp.
// grid (8, 64)
// ---------------------------------------------------------------------------
#define TS 136                      // smem row stride (halfs)
#define TILE_H (128 * TS)           // halfs per 128-row tile
#define FUSED_SMEM ((size_t)5 * TILE_H * 2 + 128 * 4)

__global__ __launch_bounds__(256, 1) void fused_attn_kernel(
    float* __restrict__ out,
    const float* __restrict__ qraw,
    const float* __restrict__ ln1w, const float* __restrict__ ln1b)
{
    extern __shared__ __align__(16) char smem_raw[];
    __half* Qs = (__half*)smem_raw;        // [128][TS]
    __half* Ks = Qs + TILE_H;              // [2][128][TS]  (rows i, cols c)
    __half* Vs = Ks + 2 * TILE_H;          // [2][128][TS]  (rows c, cols i)
    float*  inv_sm = (float*)(Vs + 2 * TILE_H);   // [128]
    float*  S32 = (float*)Ks;              // post-loop staging [128 c][132]

    int n = blockIdx.y, j0 = blockIdx.x * 128;
    const __half* Qh = g_projh + (size_t)n * PER_N;                // [j][c]
    const __half* Kh = g_projh + PER_T + (size_t)n * PER_N;        // [i][c] (scaled)
    const __half* Vh = g_projh + 2u * PER_T + (size_t)n * PER_N;   // [c][i]
    const float*  Qr = qraw + (size_t)n * PER_N;
    float2 st = g_stats[n];
    float mu = st.x, rstd = st.y;

    int tid = threadIdx.x, lane = tid & 31, warp = tid >> 5;
    int g = lane >> 2, t4 = lane & 3;
    int jw = warp * 16;                    // j-local base for this warp
    int rL = lane & 15, cL = (lane >> 4) * 8;   // ldmatrix addressing

    uint32_t qs_b = (uint32_t)__cvta_generic_to_shared(Qs);
    uint32_t ks_b = (uint32_t)__cvta_generic_to_shared(Ks);
    uint32_t vs_b = (uint32_t)__cvta_generic_to_shared(Vs);

    // prefetch Q + K0 + V0
#pragma unroll
    for (int r = 0; r < 8; r++) {
        int lin = tid + r * 256;
        int row = lin >> 4, off = lin & 15;
        uint32_t so = (uint32_t)(row * TS + off * 8) * 2u;
        cp16(qs_b + so, Qh + (size_t)(j0 + row) * 128 + off * 8);
        cp16(ks_b + so, Kh + (size_t)row * 128 + off * 8);
        cp16(vs_b + so, Vh + (size_t)row * 1024 + off * 8);
    }
    cp_commit();

    float oacc[16][4];
#pragma unroll
    for (int a = 0; a < 16; a++)
#pragma unroll
        for (int e = 0; e < 4; e++) oacc[a][e] = 0.f;
    float psum0 = 0.f, psum1 = 0.f;

    cp_wait0();
    __syncthreads();

    // cache Q A-fragments (loop-invariant): qf[kk] covers m=16 (j), k=16 (c)
    uint32_t qf[8][4];
#pragma unroll
    for (int kk = 0; kk < 8; kk++)
        ldsm_x4(qf[kk], qs_b + (uint32_t)((jw + rL) * TS + kk * 16 + cL) * 2u);

    for (int it = 0; it < 8; it++) {
        int buf = it & 1, nbuf = buf ^ 1;
        if (it < 7) {
#pragma unroll
            for (int r = 0; r < 8; r++) {
                int lin = tid + r * 256;
                int row = lin >> 4, off = lin & 15;
                uint32_t so = (uint32_t)(nbuf * TILE_H + row * TS + off * 8) * 2u;
                cp16(ks_b + so, Kh + (size_t)((it + 1) * 128 + row) * 128 + off * 8);
                cp16(vs_b + so, Vh + (size_t)row * 1024 + (it + 1) * 128 + off * 8);
            }
            cp_commit();
        }

        // ---- MMA1: sacc[j=16, i=128] = Q(regs) x K(it) ----
        uint32_t kbase = ks_b + (uint32_t)(buf * TILE_H) * 2u;
        float sacc[16][4];
#pragma unroll
        for (int a = 0; a < 16; a++)
#pragma unroll
            for (int e = 0; e < 4; e++) sacc[a][e] = 0.f;

#pragma unroll
        for (int kk = 0; kk < 8; kk++) {
            int col = kk * 16 + cL;
#pragma unroll
            for (int ni = 0; ni < 8; ni++) {
                uint32_t b[4];
                ldsm_x4(b, kbase + (uint32_t)((ni * 16 + rL) * TS + col) * 2u);
                mma_f16(sacc[ni * 2],     qf[kk][0], qf[kk][1], qf[kk][2], qf[kk][3],
                        b[0], b[2]);
                mma_f16(sacc[ni * 2 + 1], qf[kk][0], qf[kk][1], qf[kk][2], qf[kk][3],
                        b[1], b[3]);
            }
        }

        // ---- exp in registers -> A-fragments of MMA2; accumulate psum ----
        uint32_t af[8][4];
#pragma unroll
        for (int ci = 0; ci < 8; ci++) {
            float e00 = __expf(fminf(sacc[ci * 2][0], 11.f));
            float e01 = __expf(fminf(sacc[ci * 2][1], 11.f));
            float e02 = __expf(fminf(sacc[ci * 2][2], 11.f));
            float e03 = __expf(fminf(sacc[ci * 2][3], 11.f));
            float e10 = __expf(fminf(sacc[ci * 2 + 1][0], 11.f));
            float e11 = __expf(fminf(sacc[ci * 2 + 1][1], 11.f));
            float e12 = __expf(fminf(sacc[ci * 2 + 1][2], 11.f));
            float e13 = __expf(fminf(sacc[ci * 2 + 1][3], 11.f));
            psum0 += e00 + e01 + e10 + e11;       // row g
            psum1 += e02 + e03 + e12 + e13;       // row g+8
            __half2 h0 = __floats2half2_rn(e00, e01);
            __half2 h1 = __floats2half2_rn(e02, e03);
            __half2 h2 = __floats2half2_rn(e10, e11);
            __half2 h3 = __floats2half2_rn(e12, e13);
            af[ci][0] = *(uint32_t*)&h0;
            af[ci][1] = *(uint32_t*)&h1;
            af[ci][2] = *(uint32_t*)&h2;
            af[ci][3] = *(uint32_t*)&h3;
        }

        // ---- MMA2: oacc[j=16, c=128] += P(regs) x V(it) ----
        uint32_t vbase = vs_b + (uint32_t)(buf * TILE_H) * 2u;
#pragma unroll
        for (int ci = 0; ci < 8; ci++) {
            int col = ci * 16 + cL;
#pragma unroll
            for (int nc = 0; nc < 8; nc++) {
                uint32_t b[4];
                ldsm_x4(b, vbase + (uint32_t)((nc * 16 + rL) * TS + col) * 2u);
                mma_f16(oacc[nc * 2],     af[ci][0], af[ci][1], af[ci][2], af[ci][3],
                        b[0], b[2]);
                mma_f16(oacc[nc * 2 + 1], af[ci][0], af[ci][1], af[ci][2], af[ci][3],
                        b[1], b[3]);
            }
        }

        if (it < 7) cp_wait0();
        __syncthreads();
    }

    // ---- denominator: quad reduce (each warp owns full i for its j rows) ----
    psum0 += __shfl_xor_sync(0xffffffffu, psum0, 1);
    psum0 += __shfl_xor_sync(0xffffffffu, psum0, 2);
    psum1 += __shfl_xor_sync(0xffffffffu, psum1, 1);
    psum1 += __shfl_xor_sync(0xffffffffu, psum1, 2);
    if (t4 == 0) {
        inv_sm[jw + g]     = 1.f / psum0;
        inv_sm[jw + g + 8] = 1.f / psum1;
    }

    // ---- stage oacc -> S32[c][j] (K smem is dead; fp32) ----
#pragma unroll
    for (int nt = 0; nt < 16; nt++) {
        int c0 = nt * 8 + 2 * t4;
        S32[c0 * 132 + jw + g]           = oacc[nt][0];
        S32[(c0 + 1) * 132 + jw + g]     = oacc[nt][1];
        S32[c0 * 132 + jw + g + 8]       = oacc[nt][2];
        S32[(c0 + 1) * 132 + jw + g + 8] = oacc[nt][3];
    }
    __syncthreads();

    // ---- coalesced epilogue: normalize + residual ----
    float* outp = out + (size_t)n * PER_N;
    int jl = tid & 127, ch = tid >> 7;
    float invj = inv_sm[jl];
#pragma unroll 8
    for (int cc = 0; cc < 64; cc++) {
        int c = ch * 64 + cc;
        int idx = c * 1024 + j0 + jl;
        float qn = (Qr[idx] - mu) * rstd * ln1w[idx] + ln1b[idx];
        outp[idx] = S32[c * 132 + jl] * invj + qn;
    }
}

// ---------------------------------------------------------------------------
extern "C" void kernel_launch(void* const* d_in, const int* in_sizes, int n_in,
                              void* d_out, int out_size)
{
    const float* q    = (const float*)d_in[0];
    const float* k    = (const float*)d_in[1];
    const float* v    = (const float*)d_in[2];
    const float* ln1w = (const float*)d_in[3];
    const float* ln1b = (const float*)d_in[4];
    const float* ln2w = (const float*)d_in[5];
    const float* ln2b = (const float*)d_in[6];
    const float* ln3w = (const float*)d_in[7];
    const float* ln3b = (const float*)d_in[8];
    const float* wq   = (const float*)d_in[9];
    const float* bq   = (const float*)d_in[10];
    const float* wk   = (const float*)d_in[11];
    const float* bk   = (const float*)d_in[12];
    const float* wv   = (const float*)d_in[13];
    const float* bv   = (const float*)d_in[14];
    float* out = (float*)d_out;

    static bool attr_set = false;
    if (!attr_set) {
        cudaFuncSetAttribute(fused_attn_kernel,
                             cudaFuncAttributeMaxDynamicSharedMemorySize,
                             (int)FUSED_SMEM);
        attr_set = true;
    }

    ln_part_kernel<<<dim3(64, 3, 4), 256>>>(q, k, v);
    ln_finalize_kernel<<<1, 192>>>();
    conv_mma_kernel<<<dim3(8, 1, 192), 256>>>(q, k, v,
                                              ln1w, ln1b, ln2w, ln2b, ln3w, ln3b,
                                              wq, bq, wk, bk, wv, bv);
    fused_attn_kernel<<<dim3(8, 64), 256, FUSED_SMEM>>>(out, q, ln1w, ln1b);
}